// round 1
// baseline (speedup 1.0000x reference)
#include <cuda_runtime.h>
#include <cstdint>

// ---------------------------------------------------------------------------
// SlidingWindowAttention: B=32, C=384, H=W=56, WS=7, HEADS=12, hd=32
// Tokens = 32*64 windows * 49 = 100352. No padding (56 % 7 == 0).
// Pipeline:
//   im2win:  x(32,384,56,56)            -> A(100352,384)        row-major
//   gemm:    A @ qkv_w(384,1152) + b    -> QKV(100352,1152)     [q|k|v], col = s*384 + h*32 + d
//   attn:    per (window, head) softmax(qk^T*scale + bias) @ v  -> AO(100352,384)  col = h*32+d
//   gemm:    AO @ proj_w(384,384) + b   -> P(100352,384)
//   win2im:  P -> out(32,384,56,56)
// ---------------------------------------------------------------------------

#define TOKENS 100352

// scratch (static __device__ — allocation APIs are forbidden)
__device__ float g_A  [(size_t)TOKENS * 384];
__device__ float g_QKV[(size_t)TOKENS * 1152];
__device__ float g_AO [(size_t)TOKENS * 384];
__device__ float g_P  [(size_t)TOKENS * 384];

// ---------------------------------------------------------------------------
// im2win: gather one (32-channel x 1-window) tile through smem so both the
// global read (7-float runs along W) and the global write (32 contiguous
// floats along C) are reasonably coalesced.
// grid.x = 32 * 12 * 64 = 24576, 256 threads
// ---------------------------------------------------------------------------
__global__ __launch_bounds__(256) void im2win_kernel(const float* __restrict__ x,
                                                     float* __restrict__ A) {
    __shared__ float tile[32][49];
    int bx  = blockIdx.x;
    int b   = bx / 768;          // 768 = 12 ctiles * 64 windows
    int rem = bx % 768;
    int ct  = rem / 64;
    int win = rem % 64;
    int wy = win >> 3, wx = win & 7;
    int tid = threadIdx.x;

    if (tid < 224) {             // 32 channels * 7 rows
        int ci = tid / 7, iy = tid % 7;
        const float* p = x + ((size_t)(b * 384 + ct * 32 + ci) * 56 + wy * 7 + iy) * 56 + wx * 7;
#pragma unroll
        for (int ix = 0; ix < 7; ix++) tile[ci][iy * 7 + ix] = p[ix];
    }
    __syncthreads();

    size_t rowbase = (size_t)(b * 64 + win) * 49;
    for (int idx = tid; idx < 1568; idx += 256) {   // 49 tokens * 32 channels
        int n = idx >> 5, ci = idx & 31;
        A[(rowbase + n) * 384 + ct * 32 + ci] = tile[ci][n];   // stride-49 smem read: conflict-free
    }
}

// ---------------------------------------------------------------------------
// win2im: exact inverse, writing straight into d_out.
// ---------------------------------------------------------------------------
__global__ __launch_bounds__(256) void win2im_kernel(const float* __restrict__ P,
                                                     float* __restrict__ out) {
    __shared__ float tile[32][49];
    int bx  = blockIdx.x;
    int b   = bx / 768;
    int rem = bx % 768;
    int ct  = rem / 64;
    int win = rem % 64;
    int wy = win >> 3, wx = win & 7;
    int tid = threadIdx.x;

    size_t rowbase = (size_t)(b * 64 + win) * 49;
    for (int idx = tid; idx < 1568; idx += 256) {
        int n = idx >> 5, ci = idx & 31;
        tile[ci][n] = P[(rowbase + n) * 384 + ct * 32 + ci];
    }
    __syncthreads();

    if (tid < 224) {
        int ci = tid / 7, iy = tid % 7;
        float* p = out + ((size_t)(b * 384 + ct * 32 + ci) * 56 + wy * 7 + iy) * 56 + wx * 7;
#pragma unroll
        for (int ix = 0; ix < 7; ix++) p[ix] = tile[ci][iy * 7 + ix];
    }
}

// ---------------------------------------------------------------------------
// Register-tiled fp32 GEMM:  C[M x N] = A[M x 384] @ B[384 x N] + bias[N]
// BM=64, BN=128, BK=16, 256 threads, 4x8 per-thread tile.
// 32 FMA : 3 LDS.128 per k-step; float4 global loads/stores throughout.
// grid = (N/128, M/64). M=100352 (1568 tiles exact), N in {1152, 384}.
// ---------------------------------------------------------------------------
template <int N>
__global__ __launch_bounds__(256) void gemm_bias_kernel(const float* __restrict__ A,
                                                        const float* __restrict__ B,
                                                        const float* __restrict__ bias,
                                                        float* __restrict__ C) {
    __shared__ __align__(16) float As[16][64];    // [k][m]
    __shared__ __align__(16) float Bs[16][128];   // [k][n]

    int tid = threadIdx.x;
    int m0 = blockIdx.y * 64;
    int n0 = blockIdx.x * 128;
    int ty = tid >> 4;          // 0..15  -> rows ty*4 .. ty*4+3
    int tx = tid & 15;          // 0..15  -> cols tx*8 .. tx*8+7

    float acc[4][8];
#pragma unroll
    for (int i = 0; i < 4; i++)
#pragma unroll
        for (int j = 0; j < 8; j++) acc[i][j] = 0.0f;

    // A-load mapping: 64 rows x 16 cols = 1024 floats = 256 x float4
    int arow = tid >> 2;               // 0..63
    int acol = (tid & 3) << 2;         // 0,4,8,12
    const float* Aptr = A + (size_t)(m0 + arow) * 384 + acol;
    // B-load mapping: 16 rows x 128 cols = 512 float4 = 256 threads x 2
    int brow0 = tid >> 5;              // 0..7  (+8 on second pass)
    int bcol0 = (tid & 31) << 2;       // 0..124

    for (int kk = 0; kk < 384; kk += 16) {
        float4 av = *(const float4*)(Aptr + kk);
        As[acol + 0][arow] = av.x;
        As[acol + 1][arow] = av.y;
        As[acol + 2][arow] = av.z;
        As[acol + 3][arow] = av.w;
#pragma unroll
        for (int r = 0; r < 2; r++) {
            int brow = brow0 + r * 8;
            float4 bv = *(const float4*)(B + (size_t)(kk + brow) * N + n0 + bcol0);
            *(float4*)&Bs[brow][bcol0] = bv;
        }
        __syncthreads();

#pragma unroll
        for (int k = 0; k < 16; k++) {
            float4 a  = *(const float4*)&As[k][ty * 4];
            float4 b0 = *(const float4*)&Bs[k][tx * 8];
            float4 b1 = *(const float4*)&Bs[k][tx * 8 + 4];
            float ar[4] = {a.x, a.y, a.z, a.w};
            float br[8] = {b0.x, b0.y, b0.z, b0.w, b1.x, b1.y, b1.z, b1.w};
#pragma unroll
            for (int i = 0; i < 4; i++)
#pragma unroll
                for (int j = 0; j < 8; j++) acc[i][j] += ar[i] * br[j];
        }
        __syncthreads();
    }

    int colbase = n0 + tx * 8;
    float bv[8];
#pragma unroll
    for (int j = 0; j < 8; j++) bv[j] = bias[colbase + j];
#pragma unroll
    for (int i = 0; i < 4; i++) {
        size_t row = (size_t)(m0 + ty * 4 + i);
        float4 o0 = make_float4(acc[i][0] + bv[0], acc[i][1] + bv[1],
                                acc[i][2] + bv[2], acc[i][3] + bv[3]);
        float4 o1 = make_float4(acc[i][4] + bv[4], acc[i][5] + bv[5],
                                acc[i][6] + bv[6], acc[i][7] + bv[7]);
        *(float4*)(C + row * N + colbase)     = o0;
        *(float4*)(C + row * N + colbase + 4) = o1;
    }
}

// ---------------------------------------------------------------------------
// Attention: one block per (window, head). q/k/v 49x32 in padded smem,
// S = q k^T * scale + bias[rel_index], row softmax, O = S v.
// grid = (2048, 12), 256 threads, smem ~29 KB.
// ---------------------------------------------------------------------------
__global__ __launch_bounds__(256) void attn_kernel(const float* __restrict__ QKV,
                                                   const float* __restrict__ bias_table,
                                                   const int* __restrict__ rel_index,
                                                   float* __restrict__ AO) {
    __shared__ float qs[49][33];
    __shared__ float ks[49][33];
    __shared__ float vs[49][33];
    __shared__ float S[49][50];

    int w = blockIdx.x;
    int h = blockIdx.y;
    int tid = threadIdx.x;

    const float* base = QKV + (size_t)w * 49 * 1152 + h * 32;
    for (int idx = tid; idx < 1568; idx += 256) {
        int n = idx >> 5, d = idx & 31;
        const float* rp = base + n * 1152;
        qs[n][d] = rp[d];
        ks[n][d] = rp[384 + d];
        vs[n][d] = rp[768 + d];
    }
    __syncthreads();

    const float scale = 0.17677669529663687f;   // 32^-0.5
    for (int idx = tid; idx < 2401; idx += 256) {
        int n = idx / 49, m = idx % 49;
        float s = 0.0f;
#pragma unroll
        for (int d = 0; d < 32; d++) s += qs[n][d] * ks[m][d];
        S[n][m] = s * scale + bias_table[rel_index[idx] * 12 + h];
    }
    __syncthreads();

    if (tid < 49) {
        float mx = -1e30f;
#pragma unroll 7
        for (int m = 0; m < 49; m++) mx = fmaxf(mx, S[tid][m]);
        float sum = 0.0f;
#pragma unroll 7
        for (int m = 0; m < 49; m++) {
            float e = __expf(S[tid][m] - mx);
            S[tid][m] = e;
            sum += e;
        }
        float inv = 1.0f / sum;
#pragma unroll 7
        for (int m = 0; m < 49; m++) S[tid][m] *= inv;
    }
    __syncthreads();

    float* op = AO + (size_t)w * 49 * 384 + h * 32;
    for (int idx = tid; idx < 1568; idx += 256) {
        int n = idx >> 5, d = idx & 31;
        float o = 0.0f;
#pragma unroll
        for (int m = 0; m < 49; m++) o += S[n][m] * vs[m][d];
        op[n * 384 + d] = o;
    }
}

// ---------------------------------------------------------------------------
// launch
// ---------------------------------------------------------------------------
extern "C" void kernel_launch(void* const* d_in, const int* in_sizes, int n_in,
                              void* d_out, int out_size) {
    const float* x          = (const float*)d_in[0];  // (32,384,56,56)
    const float* qkv_w      = (const float*)d_in[1];  // (384,1152)
    const float* qkv_b      = (const float*)d_in[2];  // (1152,)
    const float* proj_w     = (const float*)d_in[3];  // (384,384)
    const float* proj_b     = (const float*)d_in[4];  // (384,)
    const float* bias_table = (const float*)d_in[5];  // (169,12)
    const int*   rel_index  = (const int*)d_in[6];    // (49,49)
    float* out = (float*)d_out;

    float *A, *QKV, *AO, *P;
    cudaGetSymbolAddress((void**)&A,   g_A);
    cudaGetSymbolAddress((void**)&QKV, g_QKV);
    cudaGetSymbolAddress((void**)&AO,  g_AO);
    cudaGetSymbolAddress((void**)&P,   g_P);

    im2win_kernel<<<24576, 256>>>(x, A);
    gemm_bias_kernel<1152><<<dim3(9, 1568), 256>>>(A, qkv_w, qkv_b, QKV);
    attn_kernel<<<dim3(2048, 12), 256>>>(QKV, bias_table, rel_index, AO);
    gemm_bias_kernel<384><<<dim3(3, 1568), 256>>>(AO, proj_w, proj_b, P);
    win2im_kernel<<<24576, 256>>>(P, out);
}

// round 3
// speedup vs baseline: 2.5750x; 2.5750x over previous
#include <cuda_runtime.h>
#include <cstdint>

// ---------------------------------------------------------------------------
// SlidingWindowAttention: B=32, C=384, H=W=56, WS=7, HEADS=12, hd=32
// Tokens = 100352.  GEMMs on tensor cores (TF32 mma.sync m16n8k8, with
// rna-prerounded inputs so error is pure input rounding ~5e-4 << 1e-3).
// ---------------------------------------------------------------------------

#define TOKENS 100352

__device__ float g_A  [(size_t)TOKENS * 384];   // tf32-rounded activations
__device__ float g_QKV[(size_t)TOKENS * 1152];
__device__ float g_AO [(size_t)TOKENS * 384];   // tf32-rounded attn output
__device__ float g_P  [(size_t)TOKENS * 384];
__device__ float g_Wq [384 * 1152];             // tf32-rounded qkv_w
__device__ float g_Wp [384 * 384];              // tf32-rounded proj_w

__device__ __forceinline__ float round_tf32(float x) {
    uint32_t r;
    asm("cvt.rna.tf32.f32 %0, %1;" : "=r"(r) : "f"(x));
    return __uint_as_float(r);
}

__device__ __forceinline__ void cp16(void* dst, const void* src) {
    uint32_t d = (uint32_t)__cvta_generic_to_shared(dst);
    asm volatile("cp.async.cg.shared.global [%0], [%1], 16;\n" :: "r"(d), "l"(src));
}

// ---------------------------------------------------------------------------
// one-shot rounding of BOTH weight matrices to tf32 (rna), single launch.
// n_total = 384*1152 + 384*384 = 589824.
// ---------------------------------------------------------------------------
__global__ __launch_bounds__(256) void round_w_kernel(const float* __restrict__ wq,
                                                      const float* __restrict__ wp,
                                                      float* __restrict__ oq,
                                                      float* __restrict__ op) {
    int i = blockIdx.x * 256 + threadIdx.x;
    const int NQ = 384 * 1152;
    const int NP = 384 * 384;
    if (i < NQ) oq[i] = round_tf32(wq[i]);
    int j = i - NQ;
    if (j >= 0 && j < NP) op[j] = round_tf32(wp[j]);
}

// ---------------------------------------------------------------------------
// im2win: x(32,384,56,56) -> A(100352,384) row-major, tf32-rounded.
// ---------------------------------------------------------------------------
__global__ __launch_bounds__(256) void im2win_kernel(const float* __restrict__ x,
                                                     float* __restrict__ A) {
    __shared__ float tile[32][49];
    int bx  = blockIdx.x;
    int b   = bx / 768;
    int rem = bx % 768;
    int ct  = rem / 64;
    int win = rem % 64;
    int wy = win >> 3, wx = win & 7;
    int tid = threadIdx.x;

    if (tid < 224) {
        int ci = tid / 7, iy = tid % 7;
        const float* p = x + ((size_t)(b * 384 + ct * 32 + ci) * 56 + wy * 7 + iy) * 56 + wx * 7;
#pragma unroll
        for (int ix = 0; ix < 7; ix++) tile[ci][iy * 7 + ix] = p[ix];
    }
    __syncthreads();

    size_t rowbase = (size_t)(b * 64 + win) * 49;
    for (int idx = tid; idx < 1568; idx += 256) {
        int n = idx >> 5, ci = idx & 31;
        A[(rowbase + n) * 384 + ct * 32 + ci] = round_tf32(tile[ci][n]);
    }
}

// ---------------------------------------------------------------------------
// win2im: P(100352,384) -> out(32,384,56,56)
// ---------------------------------------------------------------------------
__global__ __launch_bounds__(256) void win2im_kernel(const float* __restrict__ P,
                                                     float* __restrict__ out) {
    __shared__ float tile[32][49];
    int bx  = blockIdx.x;
    int b   = bx / 768;
    int rem = bx % 768;
    int ct  = rem / 64;
    int win = rem % 64;
    int wy = win >> 3, wx = win & 7;
    int tid = threadIdx.x;

    size_t rowbase = (size_t)(b * 64 + win) * 49;
    for (int idx = tid; idx < 1568; idx += 256) {
        int n = idx >> 5, ci = idx & 31;
        tile[ci][n] = P[(rowbase + n) * 384 + ct * 32 + ci];
    }
    __syncthreads();

    if (tid < 224) {
        int ci = tid / 7, iy = tid % 7;
        float* p = out + ((size_t)(b * 384 + ct * 32 + ci) * 56 + wy * 7 + iy) * 56 + wx * 7;
#pragma unroll
        for (int ix = 0; ix < 7; ix++) p[ix] = tile[ci][iy * 7 + ix];
    }
}

// ---------------------------------------------------------------------------
// TF32 tensor-core GEMM: C[M x N] = A[M x 384] @ B[384 x N] + bias[N]
// BM=128, BN=128, BK=16, 256 threads (8 warps, 2x4), warp tile 64x32,
// m16n8k8 tf32 mma, cp.async double buffering.
// Smem layouts bank-conflict-free for the fragment access patterns:
//   As[128][20]  (stride 20: (20g+c)%32 distinct over the 8x4 lane grid)
//   Bs[16][136]  (stride 136: (8c+g)%32 distinct)
// Inputs must already be tf32-rounded (HMMA truncation then lossless).
// ---------------------------------------------------------------------------
template <int N>
__global__ __launch_bounds__(256) void gemm_tf32_kernel(const float* __restrict__ A,
                                                        const float* __restrict__ B,
                                                        const float* __restrict__ bias,
                                                        float* __restrict__ C) {
    __shared__ __align__(16) float As[2][128][20];
    __shared__ __align__(16) float Bs[2][16][136];

    int tid  = threadIdx.x;
    int warp = tid >> 5, lane = tid & 31;
    int g = lane >> 2, c = lane & 3;
    int warp_m = (warp & 1) * 64;
    int warp_n = (warp >> 1) * 32;
    int m0 = blockIdx.y * 128;
    int n0 = blockIdx.x * 128;

    float acc[4][4][4];
#pragma unroll
    for (int i = 0; i < 4; i++)
#pragma unroll
        for (int j = 0; j < 4; j++)
#pragma unroll
            for (int t = 0; t < 4; t++) acc[i][j][t] = 0.0f;

    // global->smem mappings (512 float4 each for A and B; 2 per thread)
    int ar  = tid >> 2;            // A row 0..63 (and +64)
    int ac4 = (tid & 3) << 2;      // A col {0,4,8,12}
    int br  = tid >> 5;            // B row 0..7 (and +8)
    int bc4 = (tid & 31) << 2;     // B col {0..124}

    const float* Abase  = A + (size_t)(m0 + ar) * 384 + ac4;
    const float* Abase2 = A + (size_t)(m0 + ar + 64) * 384 + ac4;

#define ISSUE_STAGE(s, bufi) do {                                              \
        int kk = (s) * 16;                                                     \
        cp16(&As[bufi][ar][ac4],      Abase + kk);                             \
        cp16(&As[bufi][ar + 64][ac4], Abase2 + kk);                            \
        cp16(&Bs[bufi][br][bc4],      B + (size_t)(kk + br) * N + n0 + bc4);   \
        cp16(&Bs[bufi][br + 8][bc4],  B + (size_t)(kk + br + 8) * N + n0 + bc4);\
        asm volatile("cp.async.commit_group;\n");                              \
    } while (0)

    ISSUE_STAGE(0, 0);
    int buf = 0;
#pragma unroll 2
    for (int s = 0; s < 24; s++) {
        asm volatile("cp.async.wait_group 0;\n");
        __syncthreads();
        if (s + 1 < 24) ISSUE_STAGE(s + 1, buf ^ 1);

#pragma unroll
        for (int k8 = 0; k8 < 2; k8++) {
            uint32_t a[4][4], b[4][2];
#pragma unroll
            for (int i = 0; i < 4; i++) {
                int r = warp_m + g + i * 16;
                int cc = k8 * 8 + c;
                a[i][0] = __float_as_uint(As[buf][r][cc]);
                a[i][1] = __float_as_uint(As[buf][r + 8][cc]);
                a[i][2] = __float_as_uint(As[buf][r][cc + 4]);
                a[i][3] = __float_as_uint(As[buf][r + 8][cc + 4]);
            }
#pragma unroll
            for (int j = 0; j < 4; j++) {
                int col = warp_n + g + j * 8;
                int rr = k8 * 8 + c;
                b[j][0] = __float_as_uint(Bs[buf][rr][col]);
                b[j][1] = __float_as_uint(Bs[buf][rr + 4][col]);
            }
#pragma unroll
            for (int i = 0; i < 4; i++)
#pragma unroll
                for (int j = 0; j < 4; j++)
                    asm volatile(
                        "mma.sync.aligned.m16n8k8.row.col.f32.tf32.tf32.f32 "
                        "{%0,%1,%2,%3}, {%4,%5,%6,%7}, {%8,%9}, {%0,%1,%2,%3};\n"
                        : "+f"(acc[i][j][0]), "+f"(acc[i][j][1]),
                          "+f"(acc[i][j][2]), "+f"(acc[i][j][3])
                        : "r"(a[i][0]), "r"(a[i][1]), "r"(a[i][2]), "r"(a[i][3]),
                          "r"(b[j][0]), "r"(b[j][1]));
        }
        buf ^= 1;
    }
#undef ISSUE_STAGE

    // epilogue: +bias, float2 stores (fragment c0/c1 = row g cols 2c,2c+1;
    // c2/c3 = row g+8)
#pragma unroll
    for (int j = 0; j < 4; j++) {
        int col = n0 + warp_n + j * 8 + 2 * c;
        float b0v = bias[col], b1v = bias[col + 1];
#pragma unroll
        for (int i = 0; i < 4; i++) {
            int row = m0 + warp_m + i * 16 + g;
            float2 v0 = make_float2(acc[i][j][0] + b0v, acc[i][j][1] + b1v);
            float2 v1 = make_float2(acc[i][j][2] + b0v, acc[i][j][3] + b1v);
            *(float2*)(C + (size_t)row * N + col)       = v0;
            *(float2*)(C + (size_t)(row + 8) * N + col) = v1;
        }
    }
}

// ---------------------------------------------------------------------------
// Attention: one block per (window, head); epilogue tf32-rounds AO for proj.
// ---------------------------------------------------------------------------
__global__ __launch_bounds__(256) void attn_kernel(const float* __restrict__ QKV,
                                                   const float* __restrict__ bias_table,
                                                   const int* __restrict__ rel_index,
                                                   float* __restrict__ AO) {
    __shared__ float qs[49][33];
    __shared__ float ks[49][33];
    __shared__ float vs[49][33];
    __shared__ float S[49][50];

    int w = blockIdx.x;
    int h = blockIdx.y;
    int tid = threadIdx.x;

    const float* base = QKV + (size_t)w * 49 * 1152 + h * 32;
    for (int idx = tid; idx < 1568; idx += 256) {
        int n = idx >> 5, d = idx & 31;
        const float* rp = base + n * 1152;
        qs[n][d] = rp[d];
        ks[n][d] = rp[384 + d];
        vs[n][d] = rp[768 + d];
    }
    __syncthreads();

    const float scale = 0.17677669529663687f;   // 32^-0.5
    for (int idx = tid; idx < 2401; idx += 256) {
        int n = idx / 49, m = idx % 49;
        float s = 0.0f;
#pragma unroll
        for (int d = 0; d < 32; d++) s += qs[n][d] * ks[m][d];
        S[n][m] = s * scale + bias_table[rel_index[idx] * 12 + h];
    }
    __syncthreads();

    if (tid < 49) {
        float mx = -1e30f;
#pragma unroll 7
        for (int m = 0; m < 49; m++) mx = fmaxf(mx, S[tid][m]);
        float sum = 0.0f;
#pragma unroll 7
        for (int m = 0; m < 49; m++) {
            float e = __expf(S[tid][m] - mx);
            S[tid][m] = e;
            sum += e;
        }
        float inv = 1.0f / sum;
#pragma unroll 7
        for (int m = 0; m < 49; m++) S[tid][m] *= inv;
    }
    __syncthreads();

    float* op = AO + (size_t)w * 49 * 384 + h * 32;
    for (int idx = tid; idx < 1568; idx += 256) {
        int n = idx >> 5, d = idx & 31;
        float o = 0.0f;
#pragma unroll
        for (int m = 0; m < 49; m++) o += S[n][m] * vs[m][d];
        op[n * 384 + d] = round_tf32(o);
    }
}

// ---------------------------------------------------------------------------
// launch
// ---------------------------------------------------------------------------
extern "C" void kernel_launch(void* const* d_in, const int* in_sizes, int n_in,
                              void* d_out, int out_size) {
    const float* x          = (const float*)d_in[0];
    const float* qkv_w      = (const float*)d_in[1];
    const float* qkv_b      = (const float*)d_in[2];
    const float* proj_w     = (const float*)d_in[3];
    const float* proj_b     = (const float*)d_in[4];
    const float* bias_table = (const float*)d_in[5];
    const int*   rel_index  = (const int*)d_in[6];
    float* out = (float*)d_out;

    float *A, *QKV, *AO, *P, *Wq, *Wp;
    cudaGetSymbolAddress((void**)&A,   g_A);
    cudaGetSymbolAddress((void**)&QKV, g_QKV);
    cudaGetSymbolAddress((void**)&AO,  g_AO);
    cudaGetSymbolAddress((void**)&P,   g_P);
    cudaGetSymbolAddress((void**)&Wq,  g_Wq);
    cudaGetSymbolAddress((void**)&Wp,  g_Wp);

    const int NW = 384 * 1152 + 384 * 384;
    round_w_kernel<<<(NW + 255) / 256, 256>>>(qkv_w, proj_w, Wq, Wp);
    im2win_kernel<<<24576, 256>>>(x, A);
    gemm_tf32_kernel<1152><<<dim3(9, 784), 256>>>(A, Wq, qkv_b, QKV);
    attn_kernel<<<dim3(2048, 12), 256>>>(QKV, bias_table, rel_index, AO);
    gemm_tf32_kernel<384><<<dim3(3, 784), 256>>>(AO, Wp, proj_b, P);
    win2im_kernel<<<24576, 256>>>(P, out);
}

// round 5
// speedup vs baseline: 3.2631x; 1.2673x over previous
#include <cuda_runtime.h>
#include <cstdint>

// ---------------------------------------------------------------------------
// SlidingWindowAttention: B=32, C=384, H=W=56, WS=7, HEADS=12, hd=32
// Tokens = 100352.  GEMMs on tensor cores (TF32 mma.sync m16n8k8).
// Attention: register-blocked 4x4 SIMT (2 B/FMA smem intensity) + expanded
// bias table (no per-element double indirection).
// ---------------------------------------------------------------------------

#define TOKENS 100352

__device__ float g_A  [(size_t)TOKENS * 384];   // tf32-rounded activations
__device__ float g_QKV[(size_t)TOKENS * 1152];
__device__ float g_AO [(size_t)TOKENS * 384];   // tf32-rounded attn output
__device__ float g_P  [(size_t)TOKENS * 384];
__device__ float g_Wq [384 * 1152];             // tf32-rounded qkv_w
__device__ float g_Wp [384 * 384];              // tf32-rounded proj_w
__device__ float g_Bx [12 * 49 * 49];           // expanded attention bias

__device__ __forceinline__ float round_tf32(float x) {
    uint32_t r;
    asm("cvt.rna.tf32.f32 %0, %1;" : "=r"(r) : "f"(x));
    return __uint_as_float(r);
}

__device__ __forceinline__ void cp16(void* dst, const void* src) {
    uint32_t d = (uint32_t)__cvta_generic_to_shared(dst);
    asm volatile("cp.async.cg.shared.global [%0], [%1], 16;\n" :: "r"(d), "l"(src));
}

// ---------------------------------------------------------------------------
// one-shot: round both weight matrices to tf32 (rna)
// ---------------------------------------------------------------------------
__global__ __launch_bounds__(256) void round_w_kernel(const float* __restrict__ wq,
                                                      const float* __restrict__ wp,
                                                      float* __restrict__ oq,
                                                      float* __restrict__ op) {
    int i = blockIdx.x * 256 + threadIdx.x;
    const int NQ = 384 * 1152;
    const int NP = 384 * 384;
    if (i < NQ) oq[i] = round_tf32(wq[i]);
    int j = i - NQ;
    if (j >= 0 && j < NP) op[j] = round_tf32(wp[j]);
}

// ---------------------------------------------------------------------------
// one-shot: expand bias_table[rel_index] -> Bx[h][n][m] (12 x 49 x 49)
// ---------------------------------------------------------------------------
__global__ __launch_bounds__(256) void expand_bias_kernel(const float* __restrict__ bias_table,
                                                          const int* __restrict__ rel_index,
                                                          float* __restrict__ Bx) {
    int i = blockIdx.x * 256 + threadIdx.x;
    if (i < 12 * 2401) {
        int h = i / 2401, nm = i % 2401;
        Bx[i] = bias_table[rel_index[nm] * 12 + h];
    }
}

// ---------------------------------------------------------------------------
// im2win: x(32,384,56,56) -> A(100352,384) row-major, tf32-rounded.
// ---------------------------------------------------------------------------
__global__ __launch_bounds__(256) void im2win_kernel(const float* __restrict__ x,
                                                     float* __restrict__ A) {
    __shared__ float tile[32][49];
    int bx  = blockIdx.x;
    int b   = bx / 768;
    int rem = bx % 768;
    int ct  = rem / 64;
    int win = rem % 64;
    int wy = win >> 3, wx = win & 7;
    int tid = threadIdx.x;

    if (tid < 224) {
        int ci = tid / 7, iy = tid % 7;
        const float* p = x + ((size_t)(b * 384 + ct * 32 + ci) * 56 + wy * 7 + iy) * 56 + wx * 7;
#pragma unroll
        for (int ix = 0; ix < 7; ix++) tile[ci][iy * 7 + ix] = p[ix];
    }
    __syncthreads();

    size_t rowbase = (size_t)(b * 64 + win) * 49;
    for (int idx = tid; idx < 1568; idx += 256) {
        int n = idx >> 5, ci = idx & 31;
        A[(rowbase + n) * 384 + ct * 32 + ci] = round_tf32(tile[ci][n]);
    }
}

// ---------------------------------------------------------------------------
// win2im: P(100352,384) -> out(32,384,56,56)
// ---------------------------------------------------------------------------
__global__ __launch_bounds__(256) void win2im_kernel(const float* __restrict__ P,
                                                     float* __restrict__ out) {
    __shared__ float tile[32][49];
    int bx  = blockIdx.x;
    int b   = bx / 768;
    int rem = bx % 768;
    int ct  = rem / 64;
    int win = rem % 64;
    int wy = win >> 3, wx = win & 7;
    int tid = threadIdx.x;

    size_t rowbase = (size_t)(b * 64 + win) * 49;
    for (int idx = tid; idx < 1568; idx += 256) {
        int n = idx >> 5, ci = idx & 31;
        tile[ci][n] = P[(rowbase + n) * 384 + ct * 32 + ci];
    }
    __syncthreads();

    if (tid < 224) {
        int ci = tid / 7, iy = tid % 7;
        float* p = out + ((size_t)(b * 384 + ct * 32 + ci) * 56 + wy * 7 + iy) * 56 + wx * 7;
#pragma unroll
        for (int ix = 0; ix < 7; ix++) p[ix] = tile[ci][iy * 7 + ix];
    }
}

// ---------------------------------------------------------------------------
// TF32 tensor-core GEMM: C[M x N] = A[M x 384] @ B[384 x N] + bias[N]
// BM=128, BN=128, BK=16, 256 threads (8 warps, 2x4), warp tile 64x32,
// m16n8k8 tf32 mma, cp.async double buffering.
// ---------------------------------------------------------------------------
template <int N>
__global__ __launch_bounds__(256) void gemm_tf32_kernel(const float* __restrict__ A,
                                                        const float* __restrict__ B,
                                                        const float* __restrict__ bias,
                                                        float* __restrict__ C) {
    __shared__ __align__(16) float As[2][128][20];
    __shared__ __align__(16) float Bs[2][16][136];

    int tid  = threadIdx.x;
    int warp = tid >> 5, lane = tid & 31;
    int g = lane >> 2, c = lane & 3;
    int warp_m = (warp & 1) * 64;
    int warp_n = (warp >> 1) * 32;
    int m0 = blockIdx.y * 128;
    int n0 = blockIdx.x * 128;

    float acc[4][4][4];
#pragma unroll
    for (int i = 0; i < 4; i++)
#pragma unroll
        for (int j = 0; j < 4; j++)
#pragma unroll
            for (int t = 0; t < 4; t++) acc[i][j][t] = 0.0f;

    int ar  = tid >> 2;
    int ac4 = (tid & 3) << 2;
    int br  = tid >> 5;
    int bc4 = (tid & 31) << 2;

    const float* Abase  = A + (size_t)(m0 + ar) * 384 + ac4;
    const float* Abase2 = A + (size_t)(m0 + ar + 64) * 384 + ac4;

#define ISSUE_STAGE(s, bufi) do {                                              \
        int kk = (s) * 16;                                                     \
        cp16(&As[bufi][ar][ac4],      Abase + kk);                             \
        cp16(&As[bufi][ar + 64][ac4], Abase2 + kk);                            \
        cp16(&Bs[bufi][br][bc4],      B + (size_t)(kk + br) * N + n0 + bc4);   \
        cp16(&Bs[bufi][br + 8][bc4],  B + (size_t)(kk + br + 8) * N + n0 + bc4);\
        asm volatile("cp.async.commit_group;\n");                              \
    } while (0)

    ISSUE_STAGE(0, 0);
    int buf = 0;
#pragma unroll 2
    for (int s = 0; s < 24; s++) {
        asm volatile("cp.async.wait_group 0;\n");
        __syncthreads();
        if (s + 1 < 24) ISSUE_STAGE(s + 1, buf ^ 1);

#pragma unroll
        for (int k8 = 0; k8 < 2; k8++) {
            uint32_t a[4][4], b[4][2];
#pragma unroll
            for (int i = 0; i < 4; i++) {
                int r = warp_m + g + i * 16;
                int cc = k8 * 8 + c;
                a[i][0] = __float_as_uint(As[buf][r][cc]);
                a[i][1] = __float_as_uint(As[buf][r + 8][cc]);
                a[i][2] = __float_as_uint(As[buf][r][cc + 4]);
                a[i][3] = __float_as_uint(As[buf][r + 8][cc + 4]);
            }
#pragma unroll
            for (int j = 0; j < 4; j++) {
                int col = warp_n + g + j * 8;
                int rr = k8 * 8 + c;
                b[j][0] = __float_as_uint(Bs[buf][rr][col]);
                b[j][1] = __float_as_uint(Bs[buf][rr + 4][col]);
            }
#pragma unroll
            for (int i = 0; i < 4; i++)
#pragma unroll
                for (int j = 0; j < 4; j++)
                    asm volatile(
                        "mma.sync.aligned.m16n8k8.row.col.f32.tf32.tf32.f32 "
                        "{%0,%1,%2,%3}, {%4,%5,%6,%7}, {%8,%9}, {%0,%1,%2,%3};\n"
                        : "+f"(acc[i][j][0]), "+f"(acc[i][j][1]),
                          "+f"(acc[i][j][2]), "+f"(acc[i][j][3])
                        : "r"(a[i][0]), "r"(a[i][1]), "r"(a[i][2]), "r"(a[i][3]),
                          "r"(b[j][0]), "r"(b[j][1]));
        }
        buf ^= 1;
    }
#undef ISSUE_STAGE

#pragma unroll
    for (int j = 0; j < 4; j++) {
        int col = n0 + warp_n + j * 8 + 2 * c;
        float b0v = bias[col], b1v = bias[col + 1];
#pragma unroll
        for (int i = 0; i < 4; i++) {
            int row = m0 + warp_m + i * 16 + g;
            float2 v0 = make_float2(acc[i][j][0] + b0v, acc[i][j][1] + b1v);
            float2 v1 = make_float2(acc[i][j][2] + b0v, acc[i][j][3] + b1v);
            *(float2*)(C + (size_t)row * N + col)       = v0;
            *(float2*)(C + (size_t)(row + 8) * N + col) = v1;
        }
    }
}

// ---------------------------------------------------------------------------
// Attention v2: one block per (window, head), 4x4 register blocking.
// QK: 169 threads x (4n x 4m) tile, 8 LDS : 16 FMA per k.
// PV: 104 threads x (4n x 4d) tile, 8 LDS : 16 FMA per m, float4 stores.
// Odd smem strides (33 / 51) -> conflict-free strided row access.
// ---------------------------------------------------------------------------
__global__ __launch_bounds__(256) void attn_kernel(const float* __restrict__ QKV,
                                                   const float* __restrict__ Bx,
                                                   float* __restrict__ AO) {
    __shared__ float qs[49][33];
    __shared__ float ks[49][33];
    __shared__ float vs[49][33];
    __shared__ float S[49][51];

    int w = blockIdx.x;
    int h = blockIdx.y;
    int tid = threadIdx.x;

    const float* base = QKV + (size_t)w * 49 * 1152 + h * 32;
    for (int idx = tid; idx < 1568; idx += 256) {
        int n = idx >> 5, d = idx & 31;
        const float* rp = base + n * 1152;
        qs[n][d] = rp[d];
        ks[n][d] = rp[384 + d];
        vs[n][d] = rp[768 + d];
    }
    __syncthreads();

    const float scale = 0.17677669529663687f;   // 32^-0.5

    // ---- QK^T + bias: 13x13 grid of 4x4 tiles ----
    if (tid < 169) {
        int tn = tid / 13, tm = tid % 13;
        int n0 = tn * 4, m0 = tm * 4;
        int nr[4], mr[4];
#pragma unroll
        for (int i = 0; i < 4; i++) { nr[i] = min(n0 + i, 48); mr[i] = min(m0 + i, 48); }

        float acc[4][4];
#pragma unroll
        for (int i = 0; i < 4; i++)
#pragma unroll
            for (int j = 0; j < 4; j++) acc[i][j] = 0.0f;

#pragma unroll
        for (int d = 0; d < 32; d++) {
            float qv[4], kv[4];
#pragma unroll
            for (int i = 0; i < 4; i++) qv[i] = qs[nr[i]][d];
#pragma unroll
            for (int j = 0; j < 4; j++) kv[j] = ks[mr[j]][d];
#pragma unroll
            for (int i = 0; i < 4; i++)
#pragma unroll
                for (int j = 0; j < 4; j++) acc[i][j] += qv[i] * kv[j];
        }

        const float* bb = Bx + (size_t)h * 2401;
#pragma unroll
        for (int i = 0; i < 4; i++) {
            if (n0 + i < 49) {
#pragma unroll
                for (int j = 0; j < 4; j++) {
                    if (m0 + j < 49)
                        S[n0 + i][m0 + j] = acc[i][j] * scale + bb[(n0 + i) * 49 + m0 + j];
                }
            }
        }
    }
    __syncthreads();

    // ---- row softmax ----
    if (tid < 49) {
        float mx = -1e30f;
#pragma unroll 7
        for (int m = 0; m < 49; m++) mx = fmaxf(mx, S[tid][m]);
        float sum = 0.0f;
#pragma unroll 7
        for (int m = 0; m < 49; m++) {
            float e = __expf(S[tid][m] - mx);
            S[tid][m] = e;
            sum += e;
        }
        float inv = 1.0f / sum;
#pragma unroll 7
        for (int m = 0; m < 49; m++) S[tid][m] *= inv;
    }
    __syncthreads();

    // ---- P @ V: 13x8 grid of 4x4 tiles (4 n-rows x 4 d-cols) ----
    if (tid < 104) {
        int tn = tid >> 3, td = tid & 7;
        int n0 = tn * 4, d0 = td * 4;
        int nr[4];
#pragma unroll
        for (int i = 0; i < 4; i++) nr[i] = min(n0 + i, 48);

        float acc[4][4];
#pragma unroll
        for (int i = 0; i < 4; i++)
#pragma unroll
            for (int j = 0; j < 4; j++) acc[i][j] = 0.0f;

#pragma unroll 7
        for (int m = 0; m < 49; m++) {
            float sv[4], vv[4];
#pragma unroll
            for (int i = 0; i < 4; i++) sv[i] = S[nr[i]][m];
#pragma unroll
            for (int j = 0; j < 4; j++) vv[j] = vs[m][d0 + j];
#pragma unroll
            for (int i = 0; i < 4; i++)
#pragma unroll
                for (int j = 0; j < 4; j++) acc[i][j] += sv[i] * vv[j];
        }

        float* op = AO + (size_t)w * 49 * 384 + h * 32;
#pragma unroll
        for (int i = 0; i < 4; i++) {
            if (n0 + i < 49) {
                float4 o = make_float4(round_tf32(acc[i][0]), round_tf32(acc[i][1]),
                                       round_tf32(acc[i][2]), round_tf32(acc[i][3]));
                *(float4*)(op + (n0 + i) * 384 + d0) = o;
            }
        }
    }
}

// ---------------------------------------------------------------------------
// launch
// ---------------------------------------------------------------------------
extern "C" void kernel_launch(void* const* d_in, const int* in_sizes, int n_in,
                              void* d_out, int out_size) {
    const float* x          = (const float*)d_in[0];
    const float* qkv_w      = (const float*)d_in[1];
    const float* qkv_b      = (const float*)d_in[2];
    const float* proj_w     = (const float*)d_in[3];
    const float* proj_b     = (const float*)d_in[4];
    const float* bias_table = (const float*)d_in[5];
    const int*   rel_index  = (const int*)d_in[6];
    float* out = (float*)d_out;

    float *A, *QKV, *AO, *P, *Wq, *Wp, *Bx;
    cudaGetSymbolAddress((void**)&A,   g_A);
    cudaGetSymbolAddress((void**)&QKV, g_QKV);
    cudaGetSymbolAddress((void**)&AO,  g_AO);
    cudaGetSymbolAddress((void**)&P,   g_P);
    cudaGetSymbolAddress((void**)&Wq,  g_Wq);
    cudaGetSymbolAddress((void**)&Wp,  g_Wp);
    cudaGetSymbolAddress((void**)&Bx,  g_Bx);

    const int NW = 384 * 1152 + 384 * 384;
    round_w_kernel<<<(NW + 255) / 256, 256>>>(qkv_w, proj_w, Wq, Wp);
    expand_bias_kernel<<<(12 * 2401 + 255) / 256, 256>>>(bias_table, rel_index, Bx);
    im2win_kernel<<<24576, 256>>>(x, A);
    gemm_tf32_kernel<1152><<<dim3(9, 784), 256>>>(A, Wq, qkv_b, QKV);
    attn_kernel<<<dim3(2048, 12), 256>>>(QKV, Bx, AO);
    gemm_tf32_kernel<384><<<dim3(3, 784), 256>>>(AO, Wp, proj_b, P);
    win2im_kernel<<<24576, 256>>>(P, out);
}